// round 3
// baseline (speedup 1.0000x reference)
#include <cuda_runtime.h>
#include <math.h>

#define Bb   128
#define Ss   1024
#define IND  256
#define MM   64
#define DD   128
#define OUTD 128
#define ROWS (Bb*Ss)   // 131072

typedef unsigned long long u64;

__device__ __forceinline__ u64 pk2(float lo, float hi) {
    u64 r; asm("mov.b64 %0,{%1,%2};" : "=l"(r) : "f"(lo), "f"(hi)); return r;
}
__device__ __forceinline__ void upk2(float& lo, float& hi, u64 v) {
    asm("mov.b64 {%0,%1},%2;" : "=f"(lo), "=f"(hi) : "l"(v));
}
__device__ __forceinline__ u64 fma2(u64 a, u64 b, u64 c) {
    u64 d; asm("fma.rn.f32x2 %0,%1,%2,%3;" : "=l"(d) : "l"(a), "l"(b), "l"(c)); return d;
}
__device__ __forceinline__ u64 mul2(u64 a, u64 b) {
    u64 d; asm("mul.rn.f32x2 %0,%1,%2;" : "=l"(d) : "l"(a), "l"(b)); return d;
}
__device__ __forceinline__ u64 add2(u64 a, u64 b) {
    u64 d; asm("add.rn.f32x2 %0,%1,%2;" : "=l"(d) : "l"(a), "l"(b)); return d;
}

// ---------------- scratch ----------------
__device__ __align__(16) float g_Wk2[IND*MM];
__device__ __align__(16) float g_bk2[MM];
__device__ __align__(16) float g_wd[(size_t)ROWS*2*MM];  // w duplicated (w,w) pairs  67MB
__device__ __align__(16) float g_e[(size_t)ROWS*DD];     // -sigmoid(v)               67MB
__device__ __align__(16) float g_a[(size_t)ROWS*DD];     // tanh(v)                   67MB
__device__ __align__(16) float g_r[(size_t)ROWS*DD];     // read vectors              67MB

// ---------------- K0: fold Wr into memory_key ----------------
__global__ void k0_fold(const float* __restrict__ Wr, const float* __restrict__ br,
                        const float* __restrict__ Mk) {
    int gid = blockIdx.x * 256 + threadIdx.x;
    if (gid < IND*MM) {
        int i = gid >> 6, m = gid & 63;
        const float* wr = Wr + (size_t)i * DD;
        const float* mk = Mk + (size_t)m * DD;
        float s = 0.f;
        #pragma unroll 8
        for (int d = 0; d < DD; d++) s = fmaf(wr[d], mk[d], s);
        g_Wk2[i*MM + m] = s;
    } else if (gid < IND*MM + MM) {
        int m = gid - IND*MM;
        const float* mk = Mk + (size_t)m * DD;
        float s = 0.f;
        #pragma unroll 8
        for (int d = 0; d < DD; d++) s = fmaf(br[d], mk[d], s);
        g_bk2[m] = s;
    }
}

// ---------------- K1: fused  w=softmax(x@Wk2+bk2)  and  v=x@Ww+bw -> (-sigmoid, tanh) ----------------
// 128-row tile per CTA. tx (0..15): w col-pairs {tx,tx+16}; v col-pairs {tx,tx+16,tx+32,tx+48}
__global__ __launch_bounds__(256) void k1_fused(const float* __restrict__ x,
                                                const float* __restrict__ Ww,
                                                const float* __restrict__ bw) {
    __shared__ float As[16][128];
    __shared__ u64   Bw2[16][32];
    __shared__ u64   Bv2[16][64];
    __shared__ float sC[128][65];
    __shared__ float rmax[128], rinv[128];

    int tid = threadIdx.x;
    int tx = tid & 15;
    int ty = tid >> 4;
    int rowBase = blockIdx.x * 128;

    u64 accw[8][2];
    u64 accv[8][4];
    #pragma unroll
    for (int i = 0; i < 8; i++) {
        accw[i][0] = accw[i][1] = 0ull;
        #pragma unroll
        for (int j = 0; j < 4; j++) accv[i][j] = 0ull;
    }

    for (int kb = 0; kb < IND; kb += 16) {
        #pragma unroll
        for (int it = 0; it < 2; it++) {
            int f4 = tid + it * 256;
            int row = f4 >> 2, kk4 = f4 & 3;
            float4 v = *(const float4*)(x + (size_t)(rowBase + row) * IND + kb + kk4 * 4);
            As[kk4*4+0][row] = v.x; As[kk4*4+1][row] = v.y;
            As[kk4*4+2][row] = v.z; As[kk4*4+3][row] = v.w;
        }
        {
            int k = tid >> 4, n4 = tid & 15;
            float4 v = *(const float4*)(g_Wk2 + (size_t)(kb + k) * MM + n4 * 4);
            Bw2[k][n4*2+0] = pk2(v.x, v.y);
            Bw2[k][n4*2+1] = pk2(v.z, v.w);
        }
        #pragma unroll
        for (int it = 0; it < 2; it++) {
            int f4 = tid + it * 256;
            int k = f4 >> 5, n4 = f4 & 31;
            float4 v = *(const float4*)(Ww + (size_t)(kb + k) * DD + n4 * 4);
            Bv2[k][n4*2+0] = pk2(v.x, v.y);
            Bv2[k][n4*2+1] = pk2(v.z, v.w);
        }
        __syncthreads();
        #pragma unroll
        for (int k = 0; k < 16; k++) {
            u64 rw0 = Bw2[k][tx];
            u64 rw1 = Bw2[k][tx + 16];
            u64 rv[4];
            #pragma unroll
            for (int j = 0; j < 4; j++) rv[j] = Bv2[k][tx + 16*j];
            #pragma unroll
            for (int i = 0; i < 8; i++) {
                float a = As[k][ty*8 + i];
                u64 a2 = pk2(a, a);
                accw[i][0] = fma2(a2, rw0, accw[i][0]);
                accw[i][1] = fma2(a2, rw1, accw[i][1]);
                #pragma unroll
                for (int j = 0; j < 4; j++) accv[i][j] = fma2(a2, rv[j], accv[i][j]);
            }
        }
        __syncthreads();
    }

    // ---- softmax epilogue for w ----
    float accl[8][4];
    float b0 = g_bk2[2*tx], b1 = g_bk2[2*tx+1], b2 = g_bk2[2*tx+32], b3 = g_bk2[2*tx+33];
    #pragma unroll
    for (int i = 0; i < 8; i++) {
        float lo, hi;
        upk2(lo, hi, accw[i][0]);
        accl[i][0] = lo + b0; accl[i][1] = hi + b1;
        upk2(lo, hi, accw[i][1]);
        accl[i][2] = lo + b2; accl[i][3] = hi + b3;
        int row = ty*8 + i;
        sC[row][2*tx]    = accl[i][0];
        sC[row][2*tx+1]  = accl[i][1];
        sC[row][2*tx+32] = accl[i][2];
        sC[row][2*tx+33] = accl[i][3];
    }
    __syncthreads();
    {
        int row = tid >> 1, h = tid & 1;
        float mx = -1e30f;
        #pragma unroll 8
        for (int i = 0; i < 32; i++) mx = fmaxf(mx, sC[row][h*32 + i]);
        mx = fmaxf(mx, __shfl_xor_sync(0xffffffffu, mx, 1));
        float s = 0.f;
        #pragma unroll 8
        for (int i = 0; i < 32; i++) s += expf(sC[row][h*32 + i] - mx);
        s += __shfl_xor_sync(0xffffffffu, s, 1);
        if (!h) { rmax[row] = mx; rinv[row] = 1.f / s; }
    }
    __syncthreads();
    #pragma unroll
    for (int i = 0; i < 8; i++) {
        int row = ty*8 + i;
        float m = rmax[row], inv = rinv[row];
        float* wd = g_wd + (size_t)(rowBase + row) * (2*MM);
        float w0 = expf(accl[i][0]-m)*inv;
        float w1 = expf(accl[i][1]-m)*inv;
        float w2 = expf(accl[i][2]-m)*inv;
        float w3 = expf(accl[i][3]-m)*inv;
        float4 p0; p0.x = w0; p0.y = w0; p0.z = w1; p0.w = w1;
        float4 p1; p1.x = w2; p1.y = w2; p1.z = w3; p1.w = w3;
        *(float4*)(wd + 4*tx)      = p0;   // m = 2tx, 2tx+1
        *(float4*)(wd + 4*tx + 64) = p1;   // m = 2tx+32, 2tx+33
    }

    // ---- e/a epilogue for v ----
    float blo[4], bhi[4];
    #pragma unroll
    for (int j = 0; j < 4; j++) {
        int c = 2*(tx + 16*j);
        blo[j] = bw[c]; bhi[j] = bw[c+1];
    }
    #pragma unroll
    for (int i = 0; i < 8; i++) {
        size_t row = (size_t)(rowBase + ty*8 + i);
        #pragma unroll
        for (int j = 0; j < 4; j++) {
            float lo, hi;
            upk2(lo, hi, accv[i][j]);
            float v0 = lo + blo[j], v1 = hi + bhi[j];
            int c = 2*(tx + 16*j);
            // store NEGATED sigmoid (scan uses -e directly)
            *(u64*)(g_e + row*DD + c) = pk2(-1.f/(1.f+expf(-v0)), -1.f/(1.f+expf(-v1)));
            *(u64*)(g_a + row*DD + c) = pk2(tanhf(v0), tanhf(v1));
        }
    }
}

// ---------------- K2: warp-autonomous scan, 512 threads, pure fma-pipe body ----------------
// CTA = batch. 16 warps; warp owns d-range [warp*8, warp*8+8).
// lane: dp = lane&3 -> d-pair (d0 = warp*8 + dp*2); mq = lane>>2 -> m in [mq*8, mq*8+8)
__global__ __launch_bounds__(512) void k2_scan(const float* __restrict__ mv0) {
    int b = blockIdx.x;
    int warp = threadIdx.x >> 5, lane = threadIdx.x & 31;
    int dp = lane & 3, mq = lane >> 2;
    int d0 = warp * 8 + dp * 2;
    int m0 = mq * 8;

    const float* wdp = g_wd + (size_t)b * Ss * (2*MM) + 2*m0;
    const float* ep  = g_e  + (size_t)b * Ss * DD + d0;
    const float* ap  = g_a  + (size_t)b * Ss * DD + d0;
    float*       rp  = g_r  + (size_t)b * Ss * DD + d0;

    u64 Mv[8];
    #pragma unroll
    for (int j = 0; j < 8; j++)
        Mv[j] = *(const u64*)(mv0 + (size_t)(m0 + j) * DD + d0);

    longlong2 wb[2][4];       // duplicated w pairs: wb[s][q].x -> m0+2q, .y -> m0+2q+1
    u64 e2v[2], a2v[2];

#define FETCH(T, S) do { \
        const longlong2* wt = (const longlong2*)(wdp + (size_t)(T) * (2*MM)); \
        wb[S][0] = wt[0]; wb[S][1] = wt[1]; wb[S][2] = wt[2]; wb[S][3] = wt[3]; \
        e2v[S] = *(const u64*)(ep + (size_t)(T) * DD); \
        a2v[S] = *(const u64*)(ap + (size_t)(T) * DD); \
    } while (0)

    FETCH(0, 0);
    FETCH(1, 1);

    for (int t = 0; t < Ss; t += 2) {
        #pragma unroll
        for (int s = 0; s < 2; s++) {
            u64 w2[8];
            #pragma unroll
            for (int q = 0; q < 4; q++) {
                w2[2*q+0] = (u64)wb[s][q].x;
                w2[2*q+1] = (u64)wb[s][q].y;
            }
            u64 en2 = e2v[s];     // already negated
            u64 a2c = a2v[s];
            if (t + s + 2 < Ss) FETCH(t + s + 2, s);

            u64 racc0 = 0ull, racc1 = 0ull, racc2 = 0ull, racc3 = 0ull;
            #pragma unroll
            for (int j = 0; j < 8; j += 4) {
                u64 t0 = mul2(w2[j+0], Mv[j+0]);
                racc0 = add2(racc0, t0);
                Mv[j+0] = fma2(t0, en2, Mv[j+0]);
                Mv[j+0] = fma2(w2[j+0], a2c, Mv[j+0]);

                u64 t1 = mul2(w2[j+1], Mv[j+1]);
                racc1 = add2(racc1, t1);
                Mv[j+1] = fma2(t1, en2, Mv[j+1]);
                Mv[j+1] = fma2(w2[j+1], a2c, Mv[j+1]);

                u64 t2 = mul2(w2[j+2], Mv[j+2]);
                racc2 = add2(racc2, t2);
                Mv[j+2] = fma2(t2, en2, Mv[j+2]);
                Mv[j+2] = fma2(w2[j+2], a2c, Mv[j+2]);

                u64 t3 = mul2(w2[j+3], Mv[j+3]);
                racc3 = add2(racc3, t3);
                Mv[j+3] = fma2(t3, en2, Mv[j+3]);
                Mv[j+3] = fma2(w2[j+3], a2c, Mv[j+3]);
            }
            u64 rsum = add2(add2(racc0, racc1), add2(racc2, racc3));
            float r0, r1;
            upk2(r0, r1, rsum);
            r0 += __shfl_xor_sync(0xffffffffu, r0, 4);
            r0 += __shfl_xor_sync(0xffffffffu, r0, 8);
            r0 += __shfl_xor_sync(0xffffffffu, r0, 16);
            r1 += __shfl_xor_sync(0xffffffffu, r1, 4);
            r1 += __shfl_xor_sync(0xffffffffu, r1, 8);
            r1 += __shfl_xor_sync(0xffffffffu, r1, 16);
            if (mq == 0)
                *(u64*)(rp + (size_t)(t + s) * DD) = pk2(r0, r1);
        }
    }
#undef FETCH
}

// ---------------- K3: y = sigmoid(r @ Wp + bp); packed-N ----------------
__global__ __launch_bounds__(256) void k3_out(const float* __restrict__ Wp,
                                              const float* __restrict__ bp,
                                              float* __restrict__ out) {
    __shared__ float As[16][128];
    __shared__ u64   Bs2[16][64];
    int tid = threadIdx.x;
    int tx = tid & 15;
    int ty = tid >> 4;
    int rowBase = blockIdx.x * 128;

    u64 acc2[8][4];
    #pragma unroll
    for (int i = 0; i < 8; i++)
        #pragma unroll
        for (int j = 0; j < 4; j++) acc2[i][j] = 0ull;

    for (int kb = 0; kb < DD; kb += 16) {
        #pragma unroll
        for (int it = 0; it < 2; it++) {
            int f4 = tid + it * 256;
            int row = f4 >> 2, kk4 = f4 & 3;
            float4 v = *(const float4*)(g_r + (size_t)(rowBase + row) * DD + kb + kk4 * 4);
            As[kk4*4+0][row] = v.x; As[kk4*4+1][row] = v.y;
            As[kk4*4+2][row] = v.z; As[kk4*4+3][row] = v.w;
        }
        #pragma unroll
        for (int it = 0; it < 2; it++) {
            int f4 = tid + it * 256;
            int k = f4 >> 5, n4 = f4 & 31;
            float4 v = *(const float4*)(Wp + (size_t)(kb + k) * OUTD + n4 * 4);
            Bs2[k][n4*2+0] = pk2(v.x, v.y);
            Bs2[k][n4*2+1] = pk2(v.z, v.w);
        }
        __syncthreads();
        #pragma unroll
        for (int k = 0; k < 16; k++) {
            u64 rb[4];
            #pragma unroll
            for (int j = 0; j < 4; j++) rb[j] = Bs2[k][tx + 16*j];
            #pragma unroll
            for (int i = 0; i < 8; i++) {
                float a = As[k][ty*8 + i];
                u64 a2 = pk2(a, a);
                #pragma unroll
                for (int j = 0; j < 4; j++) acc2[i][j] = fma2(a2, rb[j], acc2[i][j]);
            }
        }
        __syncthreads();
    }
    float blo[4], bhi[4];
    #pragma unroll
    for (int j = 0; j < 4; j++) {
        int c = 2*(tx + 16*j);
        blo[j] = bp[c]; bhi[j] = bp[c+1];
    }
    #pragma unroll
    for (int i = 0; i < 8; i++) {
        size_t row = (size_t)(rowBase + ty*8 + i);
        #pragma unroll
        for (int j = 0; j < 4; j++) {
            float lo, hi;
            upk2(lo, hi, acc2[i][j]);
            float v0 = lo + blo[j], v1 = hi + bhi[j];
            int c = 2*(tx + 16*j);
            *(u64*)(out + row*OUTD + c) = pk2(1.f/(1.f+expf(-v0)), 1.f/(1.f+expf(-v1)));
        }
    }
}

// ---------------- launch ----------------
extern "C" void kernel_launch(void* const* d_in, const int* in_sizes, int n_in,
                              void* d_out, int out_size) {
    const float* x   = (const float*)d_in[0];
    const float* Mk  = (const float*)d_in[1];
    const float* Mv0 = (const float*)d_in[2];
    const float* Wr  = (const float*)d_in[3];
    const float* br  = (const float*)d_in[4];
    const float* Ww  = (const float*)d_in[5];
    const float* bw  = (const float*)d_in[6];
    const float* Wp  = (const float*)d_in[7];
    const float* bp  = (const float*)d_in[8];
    float* out = (float*)d_out;

    k0_fold<<<65, 256>>>(Wr, br, Mk);
    k1_fused<<<ROWS/128, 256>>>(x, Ww, bw);
    k2_scan<<<Bb, 512>>>(Mv0);
    k3_out<<<ROWS/128, 256>>>(Wp, bp, out);
}

// round 4
// speedup vs baseline: 1.0984x; 1.0984x over previous
#include <cuda_runtime.h>
#include <math.h>

#define Bb   128
#define Ss   1024
#define IND  256
#define MM   64
#define DD   128
#define OUTD 128
#define ROWS (Bb*Ss)   // 131072

typedef unsigned long long u64;

__device__ __forceinline__ u64 pk2(float lo, float hi) {
    u64 r; asm("mov.b64 %0,{%1,%2};" : "=l"(r) : "f"(lo), "f"(hi)); return r;
}
__device__ __forceinline__ void upk2(float& lo, float& hi, u64 v) {
    asm("mov.b64 {%0,%1},%2;" : "=f"(lo), "=f"(hi) : "l"(v));
}
__device__ __forceinline__ u64 fma2(u64 a, u64 b, u64 c) {
    u64 d; asm("fma.rn.f32x2 %0,%1,%2,%3;" : "=l"(d) : "l"(a), "l"(b), "l"(c)); return d;
}
__device__ __forceinline__ u64 mul2(u64 a, u64 b) {
    u64 d; asm("mul.rn.f32x2 %0,%1,%2;" : "=l"(d) : "l"(a), "l"(b)); return d;
}
__device__ __forceinline__ u64 add2(u64 a, u64 b) {
    u64 d; asm("add.rn.f32x2 %0,%1,%2;" : "=l"(d) : "l"(a), "l"(b)); return d;
}

// ---------------- scratch ----------------
__device__ __align__(16) float g_Wk2[IND*MM];
__device__ __align__(16) float g_bk2[MM];
__device__ __align__(16) float g_wd[(size_t)ROWS*2*MM];  // w duplicated (w,w) pairs  67MB
__device__ __align__(16) float g_e[(size_t)ROWS*DD];     // -sigmoid(v)               67MB
__device__ __align__(16) float g_a[(size_t)ROWS*DD];     // tanh(v)                   67MB
__device__ __align__(16) float g_r[(size_t)ROWS*DD];     // read vectors              67MB

// ---------------- K0 ----------------
__global__ void k0_fold(const float* __restrict__ Wr, const float* __restrict__ br,
                        const float* __restrict__ Mk) {
    int gid = blockIdx.x * 256 + threadIdx.x;
    if (gid < IND*MM) {
        int i = gid >> 6, m = gid & 63;
        const float* wr = Wr + (size_t)i * DD;
        const float* mk = Mk + (size_t)m * DD;
        float s = 0.f;
        #pragma unroll 8
        for (int d = 0; d < DD; d++) s = fmaf(wr[d], mk[d], s);
        g_Wk2[i*MM + m] = s;
    } else if (gid < IND*MM + MM) {
        int m = gid - IND*MM;
        const float* mk = Mk + (size_t)m * DD;
        float s = 0.f;
        #pragma unroll 8
        for (int d = 0; d < DD; d++) s = fmaf(br[d], mk[d], s);
        g_bk2[m] = s;
    }
}

// ---------------- K1a: w = softmax(x @ Wk2 + bk2); writes duplicated pairs ----------------
__global__ __launch_bounds__(256) void k1a_wsoftmax(const float* __restrict__ x) {
    __shared__ float As[16][128];
    __shared__ u64   Bs2[16][32];
    __shared__ float sC[128][65];
    __shared__ float rmax[128], rinv[128];

    int tid = threadIdx.x;
    int tx = tid & 15;
    int ty = tid >> 4;
    int rowBase = blockIdx.x * 128;

    u64 acc2[8][2];
    #pragma unroll
    for (int i = 0; i < 8; i++) { acc2[i][0] = 0ull; acc2[i][1] = 0ull; }

    for (int kb = 0; kb < IND; kb += 16) {
        #pragma unroll
        for (int it = 0; it < 2; it++) {
            int f4 = tid + it * 256;
            int row = f4 >> 2, kk4 = f4 & 3;
            float4 v = *(const float4*)(x + (size_t)(rowBase + row) * IND + kb + kk4 * 4);
            As[kk4*4+0][row] = v.x; As[kk4*4+1][row] = v.y;
            As[kk4*4+2][row] = v.z; As[kk4*4+3][row] = v.w;
        }
        {
            int k = tid >> 4, n4 = tid & 15;
            float4 v = *(const float4*)(g_Wk2 + (size_t)(kb + k) * MM + n4 * 4);
            Bs2[k][n4*2+0] = pk2(v.x, v.y);
            Bs2[k][n4*2+1] = pk2(v.z, v.w);
        }
        __syncthreads();
        #pragma unroll
        for (int k = 0; k < 16; k++) {
            u64 rb0 = Bs2[k][tx];
            u64 rb1 = Bs2[k][tx + 16];
            #pragma unroll
            for (int i = 0; i < 8; i++) {
                float a = As[k][ty*8 + i];
                u64 a2 = pk2(a, a);
                acc2[i][0] = fma2(a2, rb0, acc2[i][0]);
                acc2[i][1] = fma2(a2, rb1, acc2[i][1]);
            }
        }
        __syncthreads();
    }
    float acc[8][4];
    float b0 = g_bk2[2*tx], b1 = g_bk2[2*tx+1], b2 = g_bk2[2*tx+32], b3 = g_bk2[2*tx+33];
    #pragma unroll
    for (int i = 0; i < 8; i++) {
        float lo, hi;
        upk2(lo, hi, acc2[i][0]);
        acc[i][0] = lo + b0; acc[i][1] = hi + b1;
        upk2(lo, hi, acc2[i][1]);
        acc[i][2] = lo + b2; acc[i][3] = hi + b3;
        int row = ty*8 + i;
        sC[row][2*tx]    = acc[i][0];
        sC[row][2*tx+1]  = acc[i][1];
        sC[row][2*tx+32] = acc[i][2];
        sC[row][2*tx+33] = acc[i][3];
    }
    __syncthreads();
    {
        int row = tid >> 1, h = tid & 1;
        float mx = -1e30f;
        #pragma unroll 8
        for (int i = 0; i < 32; i++) mx = fmaxf(mx, sC[row][h*32 + i]);
        mx = fmaxf(mx, __shfl_xor_sync(0xffffffffu, mx, 1));
        float s = 0.f;
        #pragma unroll 8
        for (int i = 0; i < 32; i++) s += expf(sC[row][h*32 + i] - mx);
        s += __shfl_xor_sync(0xffffffffu, s, 1);
        if (!h) { rmax[row] = mx; rinv[row] = 1.f / s; }
    }
    __syncthreads();
    #pragma unroll
    for (int i = 0; i < 8; i++) {
        int row = ty*8 + i;
        float m = rmax[row], inv = rinv[row];
        float* wd = g_wd + (size_t)(rowBase + row) * (2*MM);
        float w0 = expf(acc[i][0]-m)*inv;
        float w1 = expf(acc[i][1]-m)*inv;
        float w2 = expf(acc[i][2]-m)*inv;
        float w3 = expf(acc[i][3]-m)*inv;
        float4 p0; p0.x = w0; p0.y = w0; p0.z = w1; p0.w = w1;
        float4 p1; p1.x = w2; p1.y = w2; p1.z = w3; p1.w = w3;
        *(float4*)(wd + 4*tx)      = p0;   // m = 2tx, 2tx+1 duplicated
        *(float4*)(wd + 4*tx + 64) = p1;   // m = 2tx+32, 2tx+33 duplicated
    }
}

// ---------------- K1b: v = x @ Ww + bw ; stores -sigmoid(v) and tanh(v) ----------------
__global__ __launch_bounds__(256) void k1b_ea(const float* __restrict__ x,
                                              const float* __restrict__ Ww,
                                              const float* __restrict__ bw) {
    __shared__ float As[16][128];
    __shared__ u64   Bs2[16][64];
    int tid = threadIdx.x;
    int tx = tid & 15;
    int ty = tid >> 4;
    int rowBase = blockIdx.x * 128;

    u64 acc2[8][4];
    #pragma unroll
    for (int i = 0; i < 8; i++)
        #pragma unroll
        for (int j = 0; j < 4; j++) acc2[i][j] = 0ull;

    for (int kb = 0; kb < IND; kb += 16) {
        #pragma unroll
        for (int it = 0; it < 2; it++) {
            int f4 = tid + it * 256;
            int row = f4 >> 2, kk4 = f4 & 3;
            float4 v = *(const float4*)(x + (size_t)(rowBase + row) * IND + kb + kk4 * 4);
            As[kk4*4+0][row] = v.x; As[kk4*4+1][row] = v.y;
            As[kk4*4+2][row] = v.z; As[kk4*4+3][row] = v.w;
        }
        #pragma unroll
        for (int it = 0; it < 2; it++) {
            int f4 = tid + it * 256;
            int k = f4 >> 5, n4 = f4 & 31;
            float4 v = *(const float4*)(Ww + (size_t)(kb + k) * DD + n4 * 4);
            Bs2[k][n4*2+0] = pk2(v.x, v.y);
            Bs2[k][n4*2+1] = pk2(v.z, v.w);
        }
        __syncthreads();
        #pragma unroll
        for (int k = 0; k < 16; k++) {
            u64 rb[4];
            #pragma unroll
            for (int j = 0; j < 4; j++) rb[j] = Bs2[k][tx + 16*j];
            #pragma unroll
            for (int i = 0; i < 8; i++) {
                float a = As[k][ty*8 + i];
                u64 a2 = pk2(a, a);
                #pragma unroll
                for (int j = 0; j < 4; j++) acc2[i][j] = fma2(a2, rb[j], acc2[i][j]);
            }
        }
        __syncthreads();
    }
    float blo[4], bhi[4];
    #pragma unroll
    for (int j = 0; j < 4; j++) {
        int c = 2*(tx + 16*j);
        blo[j] = bw[c]; bhi[j] = bw[c+1];
    }
    #pragma unroll
    for (int i = 0; i < 8; i++) {
        size_t row = (size_t)(rowBase + ty*8 + i);
        #pragma unroll
        for (int j = 0; j < 4; j++) {
            float lo, hi;
            upk2(lo, hi, acc2[i][j]);
            float v0 = lo + blo[j], v1 = hi + bhi[j];
            int c = 2*(tx + 16*j);
            *(u64*)(g_e + row*DD + c) = pk2(-1.f/(1.f+expf(-v0)), -1.f/(1.f+expf(-v1)));
            *(u64*)(g_a + row*DD + c) = pk2(tanhf(v0), tanhf(v1));
        }
    }
}

// ---------------- K2: scan, 512 thr, deferred packed r-reduction ----------------
// CTA = batch. 16 warps; warp owns d [warp*8, warp*8+8).
// lane: dp = lane&3 -> d-pair (d0 = warp*8 + dp*2); mq = lane>>2 -> m in [mq*8, mq*8+8)
__global__ __launch_bounds__(512) void k2_scan(const float* __restrict__ mv0) {
    int b = blockIdx.x;
    int warp = threadIdx.x >> 5, lane = threadIdx.x & 31;
    int dp = lane & 3, mq = lane >> 2;
    int d0 = warp * 8 + dp * 2;
    int m0 = mq * 8;

    const float* wdp = g_wd + (size_t)b * Ss * (2*MM) + 2*m0;
    const float* ep  = g_e  + (size_t)b * Ss * DD + d0;
    const float* ap  = g_a  + (size_t)b * Ss * DD + d0;
    float*       rp  = g_r  + (size_t)b * Ss * DD + d0;

    u64 Mv[8];
    #pragma unroll
    for (int j = 0; j < 8; j++)
        Mv[j] = *(const u64*)(mv0 + (size_t)(m0 + j) * DD + d0);

    // wb[s][q]: 16B = 2 duplicated w-pairs (m0+2q, m0+2q+1)
    longlong2 wb[2][4];
    u64 e2v[2], a2v[2];

#define FETCH(T, S) do { \
        const longlong2* wt = (const longlong2*)(wdp + (size_t)(T) * (2*MM)); \
        wb[S][0] = wt[0]; wb[S][1] = wt[1]; wb[S][2] = wt[2]; wb[S][3] = wt[3]; \
        e2v[S] = *(const u64*)(ep + (size_t)(T) * DD); \
        a2v[S] = *(const u64*)(ap + (size_t)(T) * DD); \
    } while (0)

    FETCH(0, 0);
    FETCH(1, 1);

    u64 rprev = 0ull;

    for (int t = 0; t < Ss; t += 2) {
        #pragma unroll
        for (int s = 0; s < 2; s++) {
            u64 en2 = e2v[s];     // already negated sigmoid
            u64 a2c = a2v[s];
            u64 wl0 = (u64)wb[s][0].x, wl1 = (u64)wb[s][0].y;
            u64 wl2 = (u64)wb[s][1].x, wl3 = (u64)wb[s][1].y;
            u64 wl4 = (u64)wb[s][2].x, wl5 = (u64)wb[s][2].y;
            u64 wl6 = (u64)wb[s][3].x, wl7 = (u64)wb[s][3].y;
            if (t + s + 2 < Ss) FETCH(t + s + 2, s);

            u64 r0, r1;
            {
                u64 t0 = mul2(wl0, Mv[0]); r0 = t0;
                Mv[0] = fma2(t0, en2, Mv[0]); Mv[0] = fma2(wl0, a2c, Mv[0]);
                u64 t1 = mul2(wl1, Mv[1]); r1 = t1;
                Mv[1] = fma2(t1, en2, Mv[1]); Mv[1] = fma2(wl1, a2c, Mv[1]);
                u64 t2 = mul2(wl2, Mv[2]); r0 = add2(r0, t2);
                Mv[2] = fma2(t2, en2, Mv[2]); Mv[2] = fma2(wl2, a2c, Mv[2]);
                u64 t3 = mul2(wl3, Mv[3]); r1 = add2(r1, t3);
                Mv[3] = fma2(t3, en2, Mv[3]); Mv[3] = fma2(wl3, a2c, Mv[3]);
                u64 t4 = mul2(wl4, Mv[4]); r0 = add2(r0, t4);
                Mv[4] = fma2(t4, en2, Mv[4]); Mv[4] = fma2(wl4, a2c, Mv[4]);
                u64 t5 = mul2(wl5, Mv[5]); r1 = add2(r1, t5);
                Mv[5] = fma2(t5, en2, Mv[5]); Mv[5] = fma2(wl5, a2c, Mv[5]);
                u64 t6 = mul2(wl6, Mv[6]); r0 = add2(r0, t6);
                Mv[6] = fma2(t6, en2, Mv[6]); Mv[6] = fma2(wl6, a2c, Mv[6]);
                u64 t7 = mul2(wl7, Mv[7]); r1 = add2(r1, t7);
                Mv[7] = fma2(t7, en2, Mv[7]); Mv[7] = fma2(wl7, a2c, Mv[7]);
            }
            // finalize PREVIOUS step's r (shfl latency off the critical path)
            {
                u64 p = rprev;
                p = add2(p, __shfl_xor_sync(0xffffffffu, p, 4));
                p = add2(p, __shfl_xor_sync(0xffffffffu, p, 8));
                p = add2(p, __shfl_xor_sync(0xffffffffu, p, 16));
                if ((t + s) > 0 && mq == 0)
                    *(u64*)(rp + (size_t)(t + s - 1) * DD) = p;
            }
            rprev = add2(r0, r1);
        }
    }
    // tail: finalize last step
    {
        u64 p = rprev;
        p = add2(p, __shfl_xor_sync(0xffffffffu, p, 4));
        p = add2(p, __shfl_xor_sync(0xffffffffu, p, 8));
        p = add2(p, __shfl_xor_sync(0xffffffffu, p, 16));
        if (mq == 0)
            *(u64*)(rp + (size_t)(Ss - 1) * DD) = p;
    }
#undef FETCH
}

// ---------------- K3: y = sigmoid(r @ Wp + bp) ----------------
__global__ __launch_bounds__(256) void k3_out(const float* __restrict__ Wp,
                                              const float* __restrict__ bp,
                                              float* __restrict__ out) {
    __shared__ float As[16][128];
    __shared__ u64   Bs2[16][64];
    int tid = threadIdx.x;
    int tx = tid & 15;
    int ty = tid >> 4;
    int rowBase = blockIdx.x * 128;

    u64 acc2[8][4];
    #pragma unroll
    for (int i = 0; i < 8; i++)
        #pragma unroll
        for (int j = 0; j < 4; j++) acc2[i][j] = 0ull;

    for (int kb = 0; kb < DD; kb += 16) {
        #pragma unroll
        for (int it = 0; it < 2; it++) {
            int f4 = tid + it * 256;
            int row = f4 >> 2, kk4 = f4 & 3;
            float4 v = *(const float4*)(g_r + (size_t)(rowBase + row) * DD + kb + kk4 * 4);
            As[kk4*4+0][row] = v.x; As[kk4*4+1][row] = v.y;
            As[kk4*4+2][row] = v.z; As[kk4*4+3][row] = v.w;
        }
        #pragma unroll
        for (int it = 0; it < 2; it++) {
            int f4 = tid + it * 256;
            int k = f4 >> 5, n4 = f4 & 31;
            float4 v = *(const float4*)(Wp + (size_t)(kb + k) * OUTD + n4 * 4);
            Bs2[k][n4*2+0] = pk2(v.x, v.y);
            Bs2[k][n4*2+1] = pk2(v.z, v.w);
        }
        __syncthreads();
        #pragma unroll
        for (int k = 0; k < 16; k++) {
            u64 rb[4];
            #pragma unroll
            for (int j = 0; j < 4; j++) rb[j] = Bs2[k][tx + 16*j];
            #pragma unroll
            for (int i = 0; i < 8; i++) {
                float a = As[k][ty*8 + i];
                u64 a2 = pk2(a, a);
                #pragma unroll
                for (int j = 0; j < 4; j++) acc2[i][j] = fma2(a2, rb[j], acc2[i][j]);
            }
        }
        __syncthreads();
    }
    float blo[4], bhi[4];
    #pragma unroll
    for (int j = 0; j < 4; j++) {
        int c = 2*(tx + 16*j);
        blo[j] = bp[c]; bhi[j] = bp[c+1];
    }
    #pragma unroll
    for (int i = 0; i < 8; i++) {
        size_t row = (size_t)(rowBase + ty*8 + i);
        #pragma unroll
        for (int j = 0; j < 4; j++) {
            float lo, hi;
            upk2(lo, hi, acc2[i][j]);
            float v0 = lo + blo[j], v1 = hi + bhi[j];
            int c = 2*(tx + 16*j);
            *(u64*)(out + row*OUTD + c) = pk2(1.f/(1.f+expf(-v0)), 1.f/(1.f+expf(-v1)));
        }
    }
}

// ---------------- launch ----------------
extern "C" void kernel_launch(void* const* d_in, const int* in_sizes, int n_in,
                              void* d_out, int out_size) {
    const float* x   = (const float*)d_in[0];
    const float* Mk  = (const float*)d_in[1];
    const float* Mv0 = (const float*)d_in[2];
    const float* Wr  = (const float*)d_in[3];
    const float* br  = (const float*)d_in[4];
    const float* Ww  = (const float*)d_in[5];
    const float* bw  = (const float*)d_in[6];
    const float* Wp  = (const float*)d_in[7];
    const float* bp  = (const float*)d_in[8];
    float* out = (float*)d_out;

    k0_fold<<<65, 256>>>(Wr, br, Mk);
    k1a_wsoftmax<<<ROWS/128, 256>>>(x);
    k1b_ea<<<ROWS/128, 256>>>(x, Ww, bw);
    k2_scan<<<Bb, 512>>>(Mv0);
    k3_out<<<ROWS/128, 256>>>(Wp, bp, out);
}